// round 4
// baseline (speedup 1.0000x reference)
#include <cuda_runtime.h>
#include <cuda_fp16.h>
#include <cstdint>

#define NBATCH 8
#define NN     2048
#define FF     128
#define UU     128
#define NP2    144      // padded B rows for main GEMM: 128 T cols + 1 Z col + 15 pad

__device__ float  g_T [NBATCH * NN * UU];
__device__ float  g_a [NBATCH * NN];
__device__ __half g_Tt[NBATCH * NP2 * NN];

__device__ __forceinline__ uint32_t smem_u32(const void* p) {
    uint32_t a;
    asm("{ .reg .u64 t; cvta.to.shared.u64 t, %1; cvt.u32.u64 %0, t; }" : "=r"(a) : "l"(p));
    return a;
}
__device__ __forceinline__ void ldm_x4(uint32_t* r, uint32_t addr) {
    asm volatile("ldmatrix.sync.aligned.m8n8.x4.shared.b16 {%0,%1,%2,%3}, [%4];"
                 : "=r"(r[0]), "=r"(r[1]), "=r"(r[2]), "=r"(r[3]) : "r"(addr));
}
__device__ __forceinline__ void ldm_x2(uint32_t* r, uint32_t addr) {
    asm volatile("ldmatrix.sync.aligned.m8n8.x2.shared.b16 {%0,%1}, [%2];"
                 : "=r"(r[0]), "=r"(r[1]) : "r"(addr));
}
__device__ __forceinline__ void mma16816(float* c, const uint32_t* a, const uint32_t* b) {
    asm volatile("mma.sync.aligned.m16n8k16.row.col.f32.f16.f16.f32 "
                 "{%0,%1,%2,%3}, {%4,%5,%6,%7}, {%8,%9}, {%0,%1,%2,%3};"
                 : "+f"(c[0]), "+f"(c[1]), "+f"(c[2]), "+f"(c[3])
                 : "r"(a[0]), "r"(a[1]), "r"(a[2]), "r"(a[3]), "r"(b[0]), "r"(b[1]));
}
__device__ __forceinline__ void sts128(uint32_t a, uint4 v) {
    asm volatile("st.shared.v4.b32 [%0], {%1,%2,%3,%4};"
                 :: "r"(a), "r"(v.x), "r"(v.y), "r"(v.z), "r"(v.w));
}
// chunk layout: [rows][64 halves] = rows * 128B, XOR swizzle on 16B units
__device__ __forceinline__ uint32_t cswz(int r, int kq) {
    return (uint32_t)(r * 128) + (uint32_t)(((kq ^ (r & 7)) & 7) << 4);
}

// ---------------- kernel A smem offsets ----------------
#define A_AH   0u
#define A_AL   32768u
#define A_BH   65536u
#define A_BL   98304u
#define A_STG  131072u      // Wf fp32 staged [f][u] stride 132 -> 67584 B; reused as T staging
#define A_BF   198656u
#define A_W1   199168u
#define A_AP   199680u      // a partials 128 x 8 fp32
#define A_DSMEM 203776

// ---------------- kernel C smem offsets ----------------
#define C_A0 0u
#define C_B0 16384u
#define C_A1 34816u
#define C_B1 51200u
#define C_DSMEM 69632       // also exactly fits eps 128 x 136 fp32

// =====================================================================
// Kernel A: T = X@Wf + bf (hi/lo fp16 HMMA), a = T.w1
// =====================================================================
__global__ void __launch_bounds__(256, 1) gat_T_kernel(
    const float* __restrict__ X, const float* __restrict__ Wf,
    const float* __restrict__ bfv, const float* __restrict__ Ws)
{
    extern __shared__ char dsm[];
    uint32_t sb = smem_u32(dsm);
    int tid = threadIdx.x, lane = tid & 31, wid = tid >> 5;
    int wm = wid & 3, wn = wid >> 2;       // warp tile: rows 32*wm, cols 64*wn
    int b = blockIdx.x >> 4;
    int i0 = (blockIdx.x & 15) << 7;

    float* bfs = reinterpret_cast<float*>(dsm + A_BF);
    float* w1s = reinterpret_cast<float*>(dsm + A_W1);
    float* stg = reinterpret_cast<float*>(dsm + A_STG);
    float* apart = reinterpret_cast<float*>(dsm + A_AP);
    if (tid < 128) { bfs[tid] = bfv[tid]; w1s[tid] = Ws[tid]; }

    // X tile -> hi/lo fp16 (chunked, swizzled)
    const float* xb = X + ((size_t)b * NN + i0) * FF;
    #pragma unroll
    for (int i = 0; i < 8; ++i) {
        int q = tid + i * 256;             // 2048 chunks of 8 floats
        int r = q >> 4, kq16 = q & 15;
        const float* src = xb + r * FF + kq16 * 8;
        float4 v0 = *reinterpret_cast<const float4*>(src);
        float4 v1 = *reinterpret_cast<const float4*>(src + 4);
        float f[8] = {v0.x, v0.y, v0.z, v0.w, v1.x, v1.y, v1.z, v1.w};
        __half h[8], l[8];
        #pragma unroll
        for (int t = 0; t < 8; ++t) {
            h[t] = __float2half_rn(f[t]);
            l[t] = __float2half_rn(f[t] - __half2float(h[t]));
        }
        uint32_t off = (uint32_t)((kq16 >> 3) * 16384) + cswz(r, kq16 & 7);
        sts128(sb + A_AH + off, *reinterpret_cast<uint4*>(h));
        sts128(sb + A_AL + off, *reinterpret_cast<uint4*>(l));
    }
    // stage Wf fp32
    #pragma unroll
    for (int i = 0; i < 16; ++i) {
        int q = tid + i * 256;
        int f = q >> 5, u = (q & 31) * 4;
        float4 v = *reinterpret_cast<const float4*>(Wf + (size_t)f * UU + u);
        *reinterpret_cast<float4*>(stg + f * 132 + u) = v;
    }
    __syncthreads();
    // transpose -> B tiles [u][f] hi/lo
    #pragma unroll
    for (int i = 0; i < 8; ++i) {
        int q = tid + i * 256;
        int u = q >> 4, kq16 = q & 15;
        int f0 = kq16 * 8;
        __half h[8], l[8];
        #pragma unroll
        for (int t = 0; t < 8; ++t) {
            float x = stg[(f0 + t) * 132 + u];
            h[t] = __float2half_rn(x);
            l[t] = __float2half_rn(x - __half2float(h[t]));
        }
        uint32_t off = (uint32_t)((kq16 >> 3) * 16384) + cswz(u, kq16 & 7);
        sts128(sb + A_BH + off, *reinterpret_cast<uint4*>(h));
        sts128(sb + A_BL + off, *reinterpret_cast<uint4*>(l));
    }
    __syncthreads();

    float acc[2][8][4];
    #pragma unroll
    for (int mi = 0; mi < 2; ++mi)
        #pragma unroll
        for (int ni = 0; ni < 8; ++ni)
            #pragma unroll
            for (int t = 0; t < 4; ++t) acc[mi][ni][t] = 0.f;

    #pragma unroll
    for (int ks = 0; ks < 8; ++ks) {
        int kq16a = ks * 2 + (lane >> 4);
        uint32_t offc_a = (uint32_t)((kq16a >> 3) * 16384);
        uint32_t ah[2][4], al[2][4];
        #pragma unroll
        for (int mi = 0; mi < 2; ++mi) {
            int r = wm * 32 + mi * 16 + (lane & 15);
            uint32_t off = offc_a + cswz(r, kq16a & 7);
            ldm_x4(ah[mi], sb + A_AH + off);
            ldm_x4(al[mi], sb + A_AL + off);
        }
        int kq16b = ks * 2 + ((lane >> 3) & 1);
        uint32_t offc_b = (uint32_t)((kq16b >> 3) * 16384);
        uint32_t bh[8][2], bl[8][2];
        #pragma unroll
        for (int nb = 0; nb < 4; ++nb) {
            int n = wn * 64 + nb * 16 + ((lane >> 4) & 1) * 8 + (lane & 7);
            uint32_t off = offc_b + cswz(n, kq16b & 7);
            ldm_x4(&bh[nb * 2][0], sb + A_BH + off);
            ldm_x4(&bl[nb * 2][0], sb + A_BL + off);
        }
        #pragma unroll
        for (int mi = 0; mi < 2; ++mi)
            #pragma unroll
            for (int ni = 0; ni < 8; ++ni) {
                mma16816(acc[mi][ni], ah[mi], bh[ni]);
                mma16816(acc[mi][ni], ah[mi], bl[ni]);
                mma16816(acc[mi][ni], al[mi], bh[ni]);
            }
    }
    __syncthreads();     // done reading stg region; reuse as T staging

    float* eps = stg;    // 128 x 132
    float pr[2][2] = {{0.f, 0.f}, {0.f, 0.f}};
    #pragma unroll
    for (int mi = 0; mi < 2; ++mi)
        #pragma unroll
        for (int ni = 0; ni < 8; ++ni) {
            int c0 = wn * 64 + ni * 8 + (lane & 3) * 2;
            int r0 = wm * 32 + mi * 16 + (lane >> 2);
            float w0 = w1s[c0], w1v = w1s[c0 + 1];
            float b0 = bfs[c0], b1 = bfs[c0 + 1];
            float v00 = acc[mi][ni][0] + b0, v01 = acc[mi][ni][1] + b1;
            float v10 = acc[mi][ni][2] + b0, v11 = acc[mi][ni][3] + b1;
            eps[r0 * 132 + c0] = v00; eps[r0 * 132 + c0 + 1] = v01;
            eps[(r0 + 8) * 132 + c0] = v10; eps[(r0 + 8) * 132 + c0 + 1] = v11;
            pr[mi][0] += v00 * w0 + v01 * w1v;
            pr[mi][1] += v10 * w0 + v11 * w1v;
        }
    #pragma unroll
    for (int mi = 0; mi < 2; ++mi)
        #pragma unroll
        for (int h = 0; h < 2; ++h) {
            int r = wm * 32 + mi * 16 + h * 8 + (lane >> 2);
            apart[r * 8 + wn * 4 + (lane & 3)] = pr[mi][h];
        }
    __syncthreads();
    if (tid < 128) {
        float s = 0.f;
        #pragma unroll
        for (int t = 0; t < 8; ++t) s += apart[tid * 8 + t];
        g_a[(size_t)b * NN + i0 + tid] = s;
    }
    float* Tb = g_T + ((size_t)b * NN + i0) * UU;
    #pragma unroll
    for (int i = 0; i < 16; ++i) {
        int q = tid + i * 256;
        int r = q >> 5, c = (q & 31) * 4;
        float4 v = *reinterpret_cast<const float4*>(eps + r * 132 + c);
        *reinterpret_cast<float4*>(Tb + (size_t)r * UU + c) = v;
    }
}

// =====================================================================
// Kernel B: e_j = exp(a_j - max_b), Tt[b][n][j] = e_j*T[j][n] (fp16, K-major)
// smt stride 138 halves -> conflict-free transpose writes
// =====================================================================
__global__ void __launch_bounds__(256, 1) gat_build_kernel()
{
    __shared__ __align__(16) __half smt[128][138];
    __shared__ float e_s[128];
    __shared__ float red[8];
    int tid = threadIdx.x, lane = tid & 31, wid = tid >> 5;
    int b = blockIdx.x >> 4;
    int j0 = (blockIdx.x & 15) << 7;
    const float* ab = g_a + (size_t)b * NN;

    float m = -1e30f;
    for (int i = tid; i < NN; i += 256) m = fmaxf(m, ab[i]);
    #pragma unroll
    for (int o = 16; o; o >>= 1) m = fmaxf(m, __shfl_xor_sync(0xFFFFFFFFu, m, o));
    if ((tid & 31) == 0) red[tid >> 5] = m;
    __syncthreads();
    float M = red[0];
    #pragma unroll
    for (int w = 1; w < 8; ++w) M = fmaxf(M, red[w]);
    if (tid < 128) e_s[tid] = expf(ab[j0 + tid] - M);
    __syncthreads();

    // transpose-load: each warp iterates rows r = wid + 8*i; lane covers u
    const float* Tb = g_T + ((size_t)b * NN + j0) * UU;
    #pragma unroll
    for (int i = 0; i < 16; ++i) {
        int r = wid + i * 8;
        float e = e_s[r];
        #pragma unroll
        for (int uu = 0; uu < 4; ++uu) {
            int u = lane + uu * 32;
            float v = Tb[(size_t)r * UU + u] * e;
            smt[u][r] = __float2half_rn(v);     // lane stride 138h = 69 words: no conflicts
        }
    }
    __syncthreads();

    __half* ttb = g_Tt + (size_t)b * NP2 * NN + j0;
    #pragma unroll
    for (int i = 0; i < 8; ++i) {
        int q = tid + i * 256;
        int u = q >> 4, c8 = q & 15;
        __half tmp[8];
        #pragma unroll
        for (int t = 0; t < 8; ++t) tmp[t] = smt[u][c8 * 8 + t];
        *reinterpret_cast<uint4*>(ttb + (size_t)u * NN + c8 * 8) = *reinterpret_cast<uint4*>(tmp);
    }
    if (tid < 128) {
        ttb[(size_t)128 * NN + tid] = __float2half_rn(e_s[tid]);
        #pragma unroll
        for (int rr = 129; rr < NP2; ++rr)
            ttb[(size_t)rr * NN + tid] = __ushort_as_half((unsigned short)0);
    }
}

// =====================================================================
// Kernel C: S = adj_fp16 @ Tt^T, out = S[:, :128] / S[:, 128]
// =====================================================================
__global__ void __launch_bounds__(256, 1) gat_main_kernel(
    const int* __restrict__ adj, float* __restrict__ out)
{
    extern __shared__ char dsm[];
    uint32_t sb = smem_u32(dsm);
    int tid = threadIdx.x, lane = tid & 31, wid = tid >> 5;
    int wm = wid & 3, wn = wid >> 2;       // warp tile rows 32*wm, cols 72*wn
    int b = blockIdx.x >> 4;
    int i0 = (blockIdx.x & 15) << 7;

    const int* adjb = adj + ((size_t)b * NN + i0) * NN;
    const __half* ttb = g_Tt + (size_t)b * NP2 * NN;

    float acc[2][9][4];
    #pragma unroll
    for (int mi = 0; mi < 2; ++mi)
        #pragma unroll
        for (int ni = 0; ni < 9; ++ni)
            #pragma unroll
            for (int t = 0; t < 4; ++t) acc[mi][ni][t] = 0.f;

    uint4 pa[8];   // adjacency prefetch: 4 chunks x 2 uint4
    uint4 pb[5];   // Tt prefetch
    int pr_r[4], pr_kq[4], pn_n[5], pn_kq[5];
    #pragma unroll
    for (int i = 0; i < 4; ++i) {
        int cid = tid + i * 256; pr_r[i] = cid >> 3; pr_kq[i] = cid & 7;
    }
    #pragma unroll
    for (int i = 0; i < 5; ++i) {
        int cid = tid + i * 256; pn_n[i] = cid >> 3; pn_kq[i] = cid & 7;
    }

    // ---- prologue: load + store chunk 0
    {
        int k0 = 0;
        #pragma unroll
        for (int i = 0; i < 4; ++i) {
            const int* src = adjb + (size_t)pr_r[i] * NN + k0 + pr_kq[i] * 8;
            pa[2 * i]     = *reinterpret_cast<const uint4*>(src);
            pa[2 * i + 1] = *reinterpret_cast<const uint4*>(src + 4);
        }
        #pragma unroll
        for (int i = 0; i < 5; ++i)
            if (pn_n[i] < NP2)
                pb[i] = *reinterpret_cast<const uint4*>(ttb + (size_t)pn_n[i] * NN + k0 + pn_kq[i] * 8);
    }
    {
        uint32_t abase = sb + C_A0, bbase = sb + C_B0;
        #pragma unroll
        for (int i = 0; i < 4; ++i) {
            uint4 u0 = pa[2 * i], u1 = pa[2 * i + 1];
            uint4 v;
            v.x = (u0.x ? 0x3C00u : 0u) | (u0.y ? 0x3C000000u : 0u);
            v.y = (u0.z ? 0x3C00u : 0u) | (u0.w ? 0x3C000000u : 0u);
            v.z = (u1.x ? 0x3C00u : 0u) | (u1.y ? 0x3C000000u : 0u);
            v.w = (u1.z ? 0x3C00u : 0u) | (u1.w ? 0x3C000000u : 0u);
            sts128(abase + cswz(pr_r[i], pr_kq[i]), v);
        }
        #pragma unroll
        for (int i = 0; i < 5; ++i)
            if (pn_n[i] < NP2) sts128(bbase + cswz(pn_n[i], pn_kq[i]), pb[i]);
    }
    __syncthreads();

    for (int ch = 0; ch < NN / 64; ++ch) {
        int buf = ch & 1;
        uint32_t abase = sb + (buf ? C_A1 : C_A0);
        uint32_t bbase = sb + (buf ? C_B1 : C_B0);

        if (ch + 1 < NN / 64) {           // prefetch next chunk into regs
            int k0 = (ch + 1) * 64;
            #pragma unroll
            for (int i = 0; i < 4; ++i) {
                const int* src = adjb + (size_t)pr_r[i] * NN + k0 + pr_kq[i] * 8;
                pa[2 * i]     = *reinterpret_cast<const uint4*>(src);
                pa[2 * i + 1] = *reinterpret_cast<const uint4*>(src + 4);
            }
            #pragma unroll
            for (int i = 0; i < 5; ++i)
                if (pn_n[i] < NP2)
                    pb[i] = *reinterpret_cast<const uint4*>(ttb + (size_t)pn_n[i] * NN + k0 + pn_kq[i] * 8);
        }

        #pragma unroll
        for (int ks = 0; ks < 4; ++ks) {
            uint32_t af[2][4];
            int kqa = ks * 2 + (lane >> 4);
            #pragma unroll
            for (int mi = 0; mi < 2; ++mi) {
                int r = wm * 32 + mi * 16 + (lane & 15);
                ldm_x4(af[mi], abase + cswz(r, kqa));
            }
            uint32_t bf[9][2];
            int kqb = ks * 2 + ((lane >> 3) & 1);
            #pragma unroll
            for (int nb = 0; nb < 4; ++nb) {
                int n = wn * 72 + nb * 16 + ((lane >> 4) & 1) * 8 + (lane & 7);
                ldm_x4(&bf[nb * 2][0], bbase + cswz(n, kqb));
            }
            {
                int n = wn * 72 + 64 + (lane & 7);
                ldm_x2(&bf[8][0], bbase + cswz(n, ks * 2 + ((lane >> 3) & 1)));
            }
            #pragma unroll
            for (int mi = 0; mi < 2; ++mi)
                #pragma unroll
                for (int ni = 0; ni < 9; ++ni)
                    mma16816(acc[mi][ni], af[mi], bf[ni]);
        }
        __syncthreads();

        if (ch + 1 < NN / 64) {
            uint32_t na = sb + (buf ? C_A0 : C_A1);
            uint32_t nb2 = sb + (buf ? C_B0 : C_B1);
            #pragma unroll
            for (int i = 0; i < 4; ++i) {
                uint4 u0 = pa[2 * i], u1 = pa[2 * i + 1];
                uint4 v;
                v.x = (u0.x ? 0x3C00u : 0u) | (u0.y ? 0x3C000000u : 0u);
                v.y = (u0.z ? 0x3C00u : 0u) | (u0.w ? 0x3C000000u : 0u);
                v.z = (u1.x ? 0x3C00u : 0u) | (u1.y ? 0x3C000000u : 0u);
                v.w = (u1.z ? 0x3C00u : 0u) | (u1.w ? 0x3C000000u : 0u);
                sts128(na + cswz(pr_r[i], pr_kq[i]), v);
            }
            #pragma unroll
            for (int i = 0; i < 5; ++i)
                if (pn_n[i] < NP2) sts128(nb2 + cswz(pn_n[i], pn_kq[i]), pb[i]);
            __syncthreads();
        }
    }

    // ---- epilogue: stage to smem (reuse buffers), divide by Z, store
    // NOTE: wn==1,ni==8 covers pad cols 136-143 -> would alias next row; skip it.
    float* eps = reinterpret_cast<float*>(dsm);   // 128 x 136 fp32
    #pragma unroll
    for (int mi = 0; mi < 2; ++mi)
        #pragma unroll
        for (int ni = 0; ni < 9; ++ni) {
            if (wn == 1 && ni == 8) continue;
            int r0 = wm * 32 + mi * 16 + (lane >> 2);
            int c0 = wn * 72 + ni * 8 + (lane & 3) * 2;
            eps[r0 * 136 + c0]     = acc[mi][ni][0];
            eps[r0 * 136 + c0 + 1] = acc[mi][ni][1];
            eps[(r0 + 8) * 136 + c0]     = acc[mi][ni][2];
            eps[(r0 + 8) * 136 + c0 + 1] = acc[mi][ni][3];
        }
    __syncthreads();
    float* ob = out + ((size_t)b * NN + i0) * UU;
    #pragma unroll
    for (int i = 0; i < 16; ++i) {
        int q = tid + i * 256;
        int r = q >> 5, c = (q & 31) * 4;
        float z = eps[r * 136 + 128];
        float inv = 1.0f / z;
        float4 v = *reinterpret_cast<const float4*>(eps + r * 136 + c);
        v.x *= inv; v.y *= inv; v.z *= inv; v.w *= inv;
        *reinterpret_cast<float4*>(ob + (size_t)r * UU + c) = v;
    }
}

// =====================================================================
extern "C" void kernel_launch(void* const* d_in, const int* in_sizes, int n_in,
                              void* d_out, int out_size)
{
    const float* X   = (const float*)d_in[0];
    const int*   adj = (const int*)d_in[1];
    const float* Wf  = (const float*)d_in[2];
    const float* bfv = (const float*)d_in[3];
    const float* Ws  = (const float*)d_in[4];
    float* out = (float*)d_out;

    cudaFuncSetAttribute(gat_T_kernel, cudaFuncAttributeMaxDynamicSharedMemorySize, A_DSMEM);
    cudaFuncSetAttribute(gat_main_kernel, cudaFuncAttributeMaxDynamicSharedMemorySize, C_DSMEM);

    gat_T_kernel<<<128, 256, A_DSMEM>>>(X, Wf, bfv, Ws);
    gat_build_kernel<<<128, 256>>>();
    gat_main_kernel<<<128, 256, C_DSMEM>>>(adj, out);
}